// round 2
// baseline (speedup 1.0000x reference)
#include <cuda_runtime.h>
#include <math.h>

#define N_NODES 30000
#define E_RAW   480000
#define E_TOT   (E_RAW + N_NODES)   // self loops appended
#define MAXH    4
#define MAXHC   512
#define TPB     256

// ---------------- scratch (static device globals: allocation-free) ----------
__device__ float g_h[N_NODES * MAXHC];     // GEMM output h = A @ W for current layer
__device__ float g_act[N_NODES * MAXHC];   // aggregated activation (layer output)
__device__ float g_asrc[N_NODES * MAXH];
__device__ float g_adst[N_NODES * MAXH];
__device__ float g_emax[N_NODES * MAXH];
__device__ float g_denom[N_NODES * MAXH];
__device__ float g_ee[E_TOT * MAXH];       // raw e, then exp(e - max)
__device__ int   g_src[E_TOT];
__device__ int   g_dst[E_TOT];
__device__ int   g_is64;                   // 1 if edge_index is int64, else int32

// ---------------- helpers ---------------------------------------------------
__device__ __forceinline__ void atomicMaxFloat(float* addr, float val) {
    if (val >= 0.0f) atomicMax((int*)addr, __float_as_int(val));
    else             atomicMin((unsigned int*)addr, __float_as_uint(val));
}
__device__ __forceinline__ int clampN(int v) {
    return v < 0 ? 0 : (v >= N_NODES ? N_NODES - 1 : v);
}

// ---------------- -1. dtype sniffer ----------------------------------------
// If edge_index is int64 (values < 30000), the int32 view has 0 at every odd
// word. If int32, odd words are live edge ids (all-zero prob ~ (1/3e4)^32).
__global__ void detect_dtype_kernel(const int* __restrict__ ei32) {
    int all_odd_zero = 1;
    for (int i = 0; i < 32; i++)
        if (ei32[2 * i + 1] != 0) { all_odd_zero = 0; break; }
    g_is64 = all_odd_zero;
}

// ---------------- 0. edge build (append self loops) -------------------------
__global__ void build_edges_kernel(const void* __restrict__ ei_raw) {
    int i = blockIdx.x * blockDim.x + threadIdx.x;
    if (i >= E_TOT) return;
    if (i < E_RAW) {
        int s, d;
        if (g_is64) {
            const long long* e = (const long long*)ei_raw;
            s = (int)e[i]; d = (int)e[E_RAW + i];
        } else {
            const int* e = (const int*)ei_raw;
            s = e[i]; d = e[E_RAW + i];
        }
        g_src[i] = clampN(s);
        g_dst[i] = clampN(d);
    } else {
        int n = i - E_RAW;
        g_src[i] = n;
        g_dst[i] = n;
    }
}

// ---------------- 1. tiled fp32 GEMM: C(g_h) = A[M,K] @ B[K,N] --------------
#define BM 64
#define BN 64
#define BK 16
__global__ void gemm_kernel(const float* __restrict__ A, const float* __restrict__ B,
                            int M, int N, int K) {
    __shared__ float As[BK][BM];
    __shared__ float Bs[BK][BN];
    int tid = threadIdx.x;            // 256 threads
    int tx = tid & 15, ty = tid >> 4; // 16x16, each does 4x4
    int rowBase = blockIdx.y * BM;
    int colBase = blockIdx.x * BN;
    float acc[4][4] = {};

    for (int k0 = 0; k0 < K; k0 += BK) {
#pragma unroll
        for (int i = 0; i < 4; i++) {           // A tile: 64x16
            int l = tid + i * 256;
            int r = l >> 4, c = l & 15;
            int gr = rowBase + r;
            As[c][r] = (gr < M) ? A[(long)gr * K + k0 + c] : 0.0f;
        }
#pragma unroll
        for (int i = 0; i < 4; i++) {           // B tile: 16x64 (N,K multiples of tile)
            int l = tid + i * 256;
            int r = l >> 6, c = l & 63;
            Bs[r][c] = B[(long)(k0 + r) * N + colBase + c];
        }
        __syncthreads();
#pragma unroll
        for (int k = 0; k < BK; k++) {
            float a[4], b[4];
#pragma unroll
            for (int i = 0; i < 4; i++) a[i] = As[k][ty * 4 + i];
#pragma unroll
            for (int j = 0; j < 4; j++) b[j] = Bs[k][tx * 4 + j];
#pragma unroll
            for (int i = 0; i < 4; i++)
#pragma unroll
                for (int j = 0; j < 4; j++) acc[i][j] += a[i] * b[j];
        }
        __syncthreads();
    }
#pragma unroll
    for (int i = 0; i < 4; i++) {
        int r = rowBase + ty * 4 + i;
        if (r >= M) continue;
#pragma unroll
        for (int j = 0; j < 4; j++)
            g_h[(long)r * N + colBase + tx * 4 + j] = acc[i][j];
    }
}

// ---------------- 2. per-(node,head) attention logits ------------------------
__global__ void node_alpha_kernel(const float* __restrict__ a_s,
                                  const float* __restrict__ a_d,
                                  int H, int C) {
    int warp = (blockIdx.x * blockDim.x + threadIdx.x) >> 5;
    int lane = threadIdx.x & 31;
    if (warp >= N_NODES * H) return;
    int n = warp / H, hh = warp - n * H;
    const float* hv = g_h + (long)n * H * C + hh * C;
    float ss = 0.f, sd = 0.f;
    for (int c = lane; c < C; c += 32) {
        float v = hv[c];
        ss += v * a_s[hh * C + c];
        sd += v * a_d[hh * C + c];
    }
#pragma unroll
    for (int o = 16; o; o >>= 1) {
        ss += __shfl_down_sync(0xffffffffu, ss, o);
        sd += __shfl_down_sync(0xffffffffu, sd, o);
    }
    if (lane == 0) { g_asrc[warp] = ss; g_adst[warp] = sd; }
}

// ---------------- 3. init per-layer buffers ---------------------------------
__global__ void init_layer_kernel(int H, int HC) {
    int i = blockIdx.x * blockDim.x + threadIdx.x;
    if (i < N_NODES * H) { g_emax[i] = -INFINITY; g_denom[i] = 0.0f; }
    if (i < N_NODES * HC) g_act[i] = 0.0f;
}

// ---------------- 4. edge logits + segment max ------------------------------
__global__ void edge_max_kernel(int H) {
    int gid = blockIdx.x * blockDim.x + threadIdx.x;
    if (gid >= E_TOT * H) return;
    int e = gid / H, hh = gid - e * H;
    int s = g_src[e], d = g_dst[e];
    float v = g_asrc[s * H + hh] + g_adst[d * H + hh];
    v = (v > 0.0f) ? v : 0.2f * v;      // leaky_relu, slope 0.2
    g_ee[gid] = v;
    atomicMaxFloat(&g_emax[d * H + hh], v);
}

// ---------------- 5. exp + segment sum --------------------------------------
__global__ void edge_exp_kernel(int H) {
    int gid = blockIdx.x * blockDim.x + threadIdx.x;
    if (gid >= E_TOT * H) return;
    int e = gid / H, hh = gid - e * H;
    int d = g_dst[e];
    float ex = __expf(g_ee[gid] - g_emax[d * H + hh]);
    g_ee[gid] = ex;
    atomicAdd(&g_denom[d * H + hh], ex);
}

// ---------------- 6. weighted message aggregation (one warp per edge) -------
__global__ void edge_agg_kernel(int H, int C) {
    int warp = (blockIdx.x * blockDim.x + threadIdx.x) >> 5;
    int lane = threadIdx.x & 31;
    if (warp >= E_TOT) return;
    int s = g_src[warp], d = g_dst[warp];
    int HC = H * C;
    float alpha_h = 0.0f;
    if (lane < H) alpha_h = g_ee[warp * H + lane] / g_denom[d * H + lane];
    const float* hs = g_h + (long)s * HC;
    float* od = g_act + (long)d * HC;
    for (int idx = lane; idx < HC; idx += 32) {
        float alpha = __shfl_sync(0xffffffffu, alpha_h, idx / C);
        atomicAdd(&od[idx], hs[idx] * alpha);
    }
}

// ---------------- 7. bias + relu (in place or to external out) --------------
__global__ void finalize_kernel(float* __restrict__ dst, const float* __restrict__ bias,
                                int total, int HC) {
    int i = blockIdx.x * blockDim.x + threadIdx.x;
    if (i >= total) return;
    float v = g_act[i] + bias[i % HC];
    dst[i] = (v > 0.0f) ? v : 0.0f;
}

// ---------------- driver -----------------------------------------------------
extern "C" void kernel_launch(void* const* d_in, const int* in_sizes, int n_in,
                              void* d_out, int out_size) {
    const float* x  = (const float*)d_in[0];
    const void*  ei = d_in[1];
    float* out = (float*)d_out;

    void* p;
    cudaGetSymbolAddress(&p, g_act);
    float* act_ptr = (float*)p;

    // layer configs: {W, a_src, a_dst, b, Fin, H, C}
    struct Cfg { const float *W, *as, *ad, *b; int Fin, H, C; };
    Cfg cfg[4] = {
        { (const float*)d_in[2],  (const float*)d_in[3],  (const float*)d_in[4],  (const float*)d_in[5],  256, 4, 128 },
        { (const float*)d_in[6],  (const float*)d_in[7],  (const float*)d_in[8],  (const float*)d_in[9],  512, 4, 128 },
        { (const float*)d_in[10], (const float*)d_in[11], (const float*)d_in[12], (const float*)d_in[13], 512, 4,  64 },
        { (const float*)d_in[14], (const float*)d_in[15], (const float*)d_in[16], (const float*)d_in[17], 256, 1,  64 },
    };

    detect_dtype_kernel<<<1, 1>>>((const int*)ei);
    build_edges_kernel<<<(E_TOT + TPB - 1) / TPB, TPB>>>(ei);

    for (int L = 0; L < 4; L++) {
        const Cfg& c = cfg[L];
        int HC = c.H * c.C;
        const float* A = (L == 0) ? x : act_ptr;

        dim3 ggrid((HC + BN - 1) / BN, (N_NODES + BM - 1) / BM);
        gemm_kernel<<<ggrid, TPB>>>(A, c.W, N_NODES, HC, c.Fin);

        int nwarps = N_NODES * c.H;
        node_alpha_kernel<<<(nwarps * 32 + TPB - 1) / TPB, TPB>>>(c.as, c.ad, c.H, c.C);

        init_layer_kernel<<<(N_NODES * HC + TPB - 1) / TPB, TPB>>>(c.H, HC);

        int eh = E_TOT * c.H;
        edge_max_kernel<<<(eh + TPB - 1) / TPB, TPB>>>(c.H);
        edge_exp_kernel<<<(eh + TPB - 1) / TPB, TPB>>>(c.H);

        edge_agg_kernel<<<(E_TOT * 32 + TPB - 1) / TPB, TPB>>>(c.H, c.C);

        float* dst = (L == 3) ? out : act_ptr;
        finalize_kernel<<<(N_NODES * HC + TPB - 1) / TPB, TPB>>>(dst, c.b, N_NODES * HC, HC);
    }
}

// round 3
// speedup vs baseline: 1.9300x; 1.9300x over previous
#include <cuda_runtime.h>
#include <math.h>

#define N_NODES 30000
#define E_RAW   480000
#define E_TOT   (E_RAW + N_NODES)   // self loops appended
#define MAXH    4
#define MAXHC   512
#define TPB     256

// ---------------- scratch (static device globals: allocation-free) ----------
__device__ float g_h[N_NODES * MAXHC];     // GEMM output h = A @ W
__device__ float g_act[N_NODES * MAXHC];   // layer output
__device__ float g_asrc[N_NODES * MAXH];
__device__ float g_adst[N_NODES * MAXH];
__device__ float g_alpha[E_TOT * MAXH];    // per-edge softmax weights (CSR order)
__device__ int   g_src[E_TOT];
__device__ int   g_dst[E_TOT];
__device__ int   g_csr_src[E_TOT];         // src ids sorted by dst
__device__ int   g_deg[N_NODES];
__device__ int   g_rowptr[N_NODES + 1];
__device__ int   g_cursor[N_NODES];
__device__ int   g_is64;

__device__ __forceinline__ int clampN(int v) {
    return v < 0 ? 0 : (v >= N_NODES ? N_NODES - 1 : v);
}

// ---------------- dtype sniffer (int32 vs int64 edge_index) -----------------
__global__ void detect_dtype_kernel(const int* __restrict__ ei32) {
    int all_odd_zero = 1;
    for (int i = 0; i < 32; i++)
        if (ei32[2 * i + 1] != 0) { all_odd_zero = 0; break; }
    g_is64 = all_odd_zero;
}

__global__ void zero_deg_kernel() {
    int i = blockIdx.x * blockDim.x + threadIdx.x;
    if (i < N_NODES) g_deg[i] = 0;
}

// ---------------- edge build (decode + self loops + degree histogram) -------
__global__ void build_edges_kernel(const void* __restrict__ ei_raw) {
    int i = blockIdx.x * blockDim.x + threadIdx.x;
    if (i >= E_TOT) return;
    int s, d;
    if (i < E_RAW) {
        if (g_is64) {
            const long long* e = (const long long*)ei_raw;
            s = (int)e[i]; d = (int)e[E_RAW + i];
        } else {
            const int* e = (const int*)ei_raw;
            s = e[i]; d = e[E_RAW + i];
        }
        s = clampN(s); d = clampN(d);
    } else {
        s = i - E_RAW; d = s;
    }
    g_src[i] = s;
    g_dst[i] = d;
    atomicAdd(&g_deg[d], 1);
}

// ---------------- exclusive scan over degrees (1 block) ---------------------
#define SCAN_T 1024
#define BINS_PER_T 30        // 1024*30 = 30720 >= 30000
__global__ void scan_kernel() {
    __shared__ int part[SCAN_T];
    int tid = threadIdx.x;
    int base = tid * BINS_PER_T;
    int s = 0;
    for (int j = 0; j < BINS_PER_T; j++) {
        int idx = base + j;
        if (idx < N_NODES) s += g_deg[idx];
    }
    part[tid] = s;
    __syncthreads();
    for (int off = 1; off < SCAN_T; off <<= 1) {
        int v = (tid >= off) ? part[tid - off] : 0;
        __syncthreads();
        part[tid] += v;
        __syncthreads();
    }
    int run = part[tid] - s;    // exclusive prefix
    for (int j = 0; j < BINS_PER_T; j++) {
        int idx = base + j;
        if (idx < N_NODES) {
            g_rowptr[idx] = run;
            g_cursor[idx] = run;
            run += g_deg[idx];
        }
    }
    if (tid == 0) g_rowptr[N_NODES] = E_TOT;
}

// ---------------- scatter into CSR ------------------------------------------
__global__ void scatter_kernel() {
    int e = blockIdx.x * blockDim.x + threadIdx.x;
    if (e >= E_TOT) return;
    int d = g_dst[e];
    int pos = atomicAdd(&g_cursor[d], 1);
    g_csr_src[pos] = g_src[e];
}

// ---------------- GEMM: g_h[M,N] = A[M,K] @ B[K,N] --------------------------
#define BM 128
#define BN 64
#define BK 16
__global__ __launch_bounds__(256) void gemm_kernel(
        const float* __restrict__ A, const float* __restrict__ B,
        int M, int N, int K) {
    __shared__ float As[2][BK][BM];
    __shared__ float Bs[2][BK][BN];
    int tid = threadIdx.x;
    int tx = tid & 15;           // 16 col groups (4 cols each)
    int ty = tid >> 4;           // 16 row groups (8 rows each)
    int rowBase = blockIdx.y * BM;
    int colBase = blockIdx.x * BN;

    float acc[8][4] = {};

    // A-tile mapping: 512 float4 -> 2 per thread
    int af0 = tid, af1 = tid + 256;
    int ar0 = af0 >> 2, ac0 = (af0 & 3) * 4;
    int ar1 = af1 >> 2, ac1 = (af1 & 3) * 4;
    // B-tile mapping: 256 float4 -> 1 per thread
    int br = tid >> 4, bc = (tid & 15) * 4;

    // load tile 0
    {
        float4 a0 = (rowBase + ar0 < M) ? *(const float4*)&A[(long)(rowBase + ar0) * K + ac0]
                                        : make_float4(0.f, 0.f, 0.f, 0.f);
        float4 a1 = (rowBase + ar1 < M) ? *(const float4*)&A[(long)(rowBase + ar1) * K + ac1]
                                        : make_float4(0.f, 0.f, 0.f, 0.f);
        As[0][ac0 + 0][ar0] = a0.x; As[0][ac0 + 1][ar0] = a0.y;
        As[0][ac0 + 2][ar0] = a0.z; As[0][ac0 + 3][ar0] = a0.w;
        As[0][ac1 + 0][ar1] = a1.x; As[0][ac1 + 1][ar1] = a1.y;
        As[0][ac1 + 2][ar1] = a1.z; As[0][ac1 + 3][ar1] = a1.w;
        float4 b = *(const float4*)&B[(long)br * N + colBase + bc];
        *(float4*)&Bs[0][br][bc] = b;
    }
    __syncthreads();

    int buf = 0;
    for (int k0 = 0; k0 < K; k0 += BK) {
        float4 pa0, pa1, pb;
        bool next = (k0 + BK < K);
        if (next) {
            int kn = k0 + BK;
            pa0 = (rowBase + ar0 < M) ? *(const float4*)&A[(long)(rowBase + ar0) * K + kn + ac0]
                                      : make_float4(0.f, 0.f, 0.f, 0.f);
            pa1 = (rowBase + ar1 < M) ? *(const float4*)&A[(long)(rowBase + ar1) * K + kn + ac1]
                                      : make_float4(0.f, 0.f, 0.f, 0.f);
            pb  = *(const float4*)&B[(long)(kn + br) * N + colBase + bc];
        }
#pragma unroll
        for (int k = 0; k < BK; k++) {
            float4 b4 = *(float4*)&Bs[buf][k][tx * 4];
            float4 a40 = *(float4*)&As[buf][k][ty * 8];
            float4 a41 = *(float4*)&As[buf][k][ty * 8 + 4];
            float a[8] = {a40.x, a40.y, a40.z, a40.w, a41.x, a41.y, a41.z, a41.w};
            float b[4] = {b4.x, b4.y, b4.z, b4.w};
#pragma unroll
            for (int i = 0; i < 8; i++)
#pragma unroll
                for (int j = 0; j < 4; j++) acc[i][j] += a[i] * b[j];
        }
        if (next) {
            int nb = buf ^ 1;
            As[nb][ac0 + 0][ar0] = pa0.x; As[nb][ac0 + 1][ar0] = pa0.y;
            As[nb][ac0 + 2][ar0] = pa0.z; As[nb][ac0 + 3][ar0] = pa0.w;
            As[nb][ac1 + 0][ar1] = pa1.x; As[nb][ac1 + 1][ar1] = pa1.y;
            As[nb][ac1 + 2][ar1] = pa1.z; As[nb][ac1 + 3][ar1] = pa1.w;
            *(float4*)&Bs[nb][br][bc] = pb;
        }
        __syncthreads();
        buf ^= 1;
    }

#pragma unroll
    for (int i = 0; i < 8; i++) {
        int r = rowBase + ty * 8 + i;
        if (r < M) {
            float4 v = make_float4(acc[i][0], acc[i][1], acc[i][2], acc[i][3]);
            *(float4*)&g_h[(long)r * N + colBase + tx * 4] = v;
        }
    }
}

// ---------------- per-(node,head) attention logits ---------------------------
__global__ void node_alpha_kernel(const float* __restrict__ a_s,
                                  const float* __restrict__ a_d,
                                  int H, int C) {
    int warp = (blockIdx.x * blockDim.x + threadIdx.x) >> 5;
    int lane = threadIdx.x & 31;
    if (warp >= N_NODES * H) return;
    int n = warp / H, hh = warp - n * H;
    const float* hv = g_h + (long)n * H * C + hh * C;
    float ss = 0.f, sd = 0.f;
    for (int c = lane; c < C; c += 32) {
        float v = hv[c];
        ss += v * a_s[hh * C + c];
        sd += v * a_d[hh * C + c];
    }
#pragma unroll
    for (int o = 16; o; o >>= 1) {
        ss += __shfl_down_sync(0xffffffffu, ss, o);
        sd += __shfl_down_sync(0xffffffffu, sd, o);
    }
    if (lane == 0) { g_asrc[warp] = ss; g_adst[warp] = sd; }
}

// ---------------- per-dst softmax: write alpha per CSR edge ------------------
template <int H>
__global__ void attn_alpha_kernel() {     // grid = N_NODES, block = 128
    int d = blockIdx.x;
    int tid = threadIdx.x;
    int lane = tid & 31, wid = tid >> 5;
    int start = g_rowptr[d], end = g_rowptr[d + 1];
    int deg = end - start;

    __shared__ float red[H][4];
    __shared__ float bmax[H], bsum[H];

    float adst[H];
#pragma unroll
    for (int h = 0; h < H; h++) adst[h] = g_adst[d * H + h];

    // pass 1: max
    float lmax[H];
#pragma unroll
    for (int h = 0; h < H; h++) lmax[h] = -INFINITY;
    for (int i = tid; i < deg; i += 128) {
        int s = g_csr_src[start + i];
#pragma unroll
        for (int h = 0; h < H; h++) {
            float v = g_asrc[s * H + h] + adst[h];
            v = (v > 0.f) ? v : 0.2f * v;
            lmax[h] = fmaxf(lmax[h], v);
        }
    }
#pragma unroll
    for (int h = 0; h < H; h++) {
#pragma unroll
        for (int o = 16; o; o >>= 1) lmax[h] = fmaxf(lmax[h], __shfl_down_sync(0xffffffffu, lmax[h], o));
        if (lane == 0) red[h][wid] = lmax[h];
    }
    __syncthreads();
    if (tid < H) {
        float m = fmaxf(fmaxf(red[tid][0], red[tid][1]), fmaxf(red[tid][2], red[tid][3]));
        bmax[tid] = m;
    }
    __syncthreads();

    // pass 2: sum of exp
    float lsum[H];
#pragma unroll
    for (int h = 0; h < H; h++) lsum[h] = 0.f;
    for (int i = tid; i < deg; i += 128) {
        int s = g_csr_src[start + i];
#pragma unroll
        for (int h = 0; h < H; h++) {
            float v = g_asrc[s * H + h] + adst[h];
            v = (v > 0.f) ? v : 0.2f * v;
            lsum[h] += __expf(v - bmax[h]);
        }
    }
#pragma unroll
    for (int h = 0; h < H; h++) {
#pragma unroll
        for (int o = 16; o; o >>= 1) lsum[h] += __shfl_down_sync(0xffffffffu, lsum[h], o);
        if (lane == 0) red[h][wid] = lsum[h];
    }
    __syncthreads();
    if (tid < H) bsum[tid] = 1.f / (red[tid][0] + red[tid][1] + red[tid][2] + red[tid][3]);
    __syncthreads();

    // pass 3: write alpha
    for (int i = tid; i < deg; i += 128) {
        int s = g_csr_src[start + i];
#pragma unroll
        for (int h = 0; h < H; h++) {
            float v = g_asrc[s * H + h] + adst[h];
            v = (v > 0.f) ? v : 0.2f * v;
            g_alpha[(long)(start + i) * H + h] = __expf(v - bmax[h]) * bsum[h];
        }
    }
}

// ---------------- gather-aggregate + bias + relu -----------------------------
template <int H, int C>
__global__ void agg_kernel(const float* __restrict__ bias, float* __restrict__ out) {
    constexpr int HC = H * C;
    constexpr int NV = HC / 4;          // float4s per row
    int d = blockIdx.x;
    int tid = threadIdx.x;
    if (tid >= NV) return;
    int c4 = tid * 4;
    int head = c4 / C;
    int start = g_rowptr[d], end = g_rowptr[d + 1];

    float4 acc = make_float4(0.f, 0.f, 0.f, 0.f);
    for (int pos = start; pos < end; pos++) {
        int s = g_csr_src[pos];
        float al = g_alpha[(long)pos * H + head];
        float4 hv = *(const float4*)&g_h[(long)s * HC + c4];
        acc.x += hv.x * al; acc.y += hv.y * al;
        acc.z += hv.z * al; acc.w += hv.w * al;
    }
    float4 bv = *(const float4*)&bias[c4];
    acc.x = fmaxf(acc.x + bv.x, 0.f);
    acc.y = fmaxf(acc.y + bv.y, 0.f);
    acc.z = fmaxf(acc.z + bv.z, 0.f);
    acc.w = fmaxf(acc.w + bv.w, 0.f);
    *(float4*)&out[(long)d * HC + c4] = acc;
}

// ---------------- driver -----------------------------------------------------
extern "C" void kernel_launch(void* const* d_in, const int* in_sizes, int n_in,
                              void* d_out, int out_size) {
    const float* x  = (const float*)d_in[0];
    const void*  ei = d_in[1];
    float* out = (float*)d_out;

    void* p;
    cudaGetSymbolAddress(&p, g_act);
    float* act_ptr = (float*)p;

    struct Cfg { const float *W, *as, *ad, *b; int Fin, H, C; };
    Cfg cfg[4] = {
        { (const float*)d_in[2],  (const float*)d_in[3],  (const float*)d_in[4],  (const float*)d_in[5],  256, 4, 128 },
        { (const float*)d_in[6],  (const float*)d_in[7],  (const float*)d_in[8],  (const float*)d_in[9],  512, 4, 128 },
        { (const float*)d_in[10], (const float*)d_in[11], (const float*)d_in[12], (const float*)d_in[13], 512, 4,  64 },
        { (const float*)d_in[14], (const float*)d_in[15], (const float*)d_in[16], (const float*)d_in[17], 256, 1,  64 },
    };

    detect_dtype_kernel<<<1, 1>>>((const int*)ei);
    zero_deg_kernel<<<(N_NODES + TPB - 1) / TPB, TPB>>>();
    build_edges_kernel<<<(E_TOT + TPB - 1) / TPB, TPB>>>(ei);
    scan_kernel<<<1, SCAN_T>>>();
    scatter_kernel<<<(E_TOT + TPB - 1) / TPB, TPB>>>();

    for (int L = 0; L < 4; L++) {
        const Cfg& c = cfg[L];
        int HC = c.H * c.C;
        const float* A = (L == 0) ? x : act_ptr;

        dim3 ggrid(HC / BN, (N_NODES + BM - 1) / BM);
        gemm_kernel<<<ggrid, 256>>>(A, c.W, N_NODES, HC, c.Fin);

        int nwarps = N_NODES * c.H;
        node_alpha_kernel<<<(nwarps * 32 + TPB - 1) / TPB, TPB>>>(c.as, c.ad, c.H, c.C);

        float* dst = (L == 3) ? out : act_ptr;
        switch (L) {
            case 0:
                attn_alpha_kernel<4><<<N_NODES, 128>>>();
                agg_kernel<4, 128><<<N_NODES, 128>>>(c.b, dst);
                break;
            case 1:
                attn_alpha_kernel<4><<<N_NODES, 128>>>();
                agg_kernel<4, 128><<<N_NODES, 128>>>(c.b, dst);
                break;
            case 2:
                attn_alpha_kernel<4><<<N_NODES, 128>>>();
                agg_kernel<4, 64><<<N_NODES, 64>>>(c.b, dst);
                break;
            case 3:
                attn_alpha_kernel<1><<<N_NODES, 128>>>();
                agg_kernel<1, 64><<<N_NODES, 32>>>(c.b, dst);
                break;
        }
    }
}